// round 13
// baseline (speedup 1.0000x reference)
#include <cuda_runtime.h>
#include <math.h>
#include <cstdint>

#define BATCH   1024
#define EMBD    512
#define RNND    512
#define GATES   2048
#define VOCABO  11998
#define FEATSD  4096
#define TSTEPS  15

typedef unsigned long long u64;

// ---------------- scratch (__device__ globals; no runtime allocation) ----------
__device__ float g_x[BATCH * EMBD];
__device__ float g_h[BATCH * RNND];
__device__ float g_c[BATCH * RNND];
__device__ float g_gates[BATCH * GATES];
__device__ u64   g_amax[BATCH];
__device__ int   g_words[BATCH];

// ---------------- packed f32x2 helpers ------------------------------------------
__device__ __forceinline__ u64 pack2(float lo, float hi) {
    u64 r; asm("mov.b64 %0, {%1, %2};" : "=l"(r) : "f"(lo), "f"(hi)); return r;
}
__device__ __forceinline__ void unpack2(u64 v, float& lo, float& hi) {
    asm("mov.b64 {%0, %1}, %2;" : "=f"(lo), "=f"(hi) : "l"(v));
}
__device__ __forceinline__ void ffma2(u64& d, u64 a, u64 b) {
    asm("fma.rn.f32x2 %0, %1, %2, %0;" : "+l"(d) : "l"(a), "l"(b));
}

// ---------------- activations ---------------------------------------------------
__device__ __forceinline__ float sigm_f(float x) { return 1.0f / (1.0f + expf(-x)); }
__device__ __forceinline__ float tanh_f(float x) {
    float e = expf(-2.0f * fabsf(x));
    float t = (1.0f - e) / (1.0f + e);
    return copysignf(t, x);
}
__device__ __forceinline__ u64 amax_key(float v, int n) {
    unsigned u = __float_as_uint(v);
    u = (u & 0x80000000u) ? ~u : (u | 0x80000000u);
    return ((u64)u << 32) | (u64)(0xFFFFFFFFu - (unsigned)n);
}

// ================================================================================
// Kernel 1: g_x = relu(img[1024,4096] @ W_feats^T + b); zero h, c. (proven R12)
// ================================================================================
__global__ __launch_bounds__(256) void k_prime(const float* __restrict__ A,
                                               const float* __restrict__ Bw,
                                               const float* __restrict__ bias) {
    __shared__ __align__(16) float As[32][68];
    __shared__ __align__(16) float Bs[32][68];
    const int tid = threadIdx.x;
    const int bm = blockIdx.y * 64, bn = blockIdx.x * 64;
    const int lr = tid >> 3, lk = (tid & 7) << 2;
    const int m0 = (tid >> 4) << 2, n0 = (tid & 15) << 2;
    u64 acc2[4][2] = {};

    for (int s = 0; s < FEATSD / 32; s++) {
        const int ka = s * 32 + lk;
        float4 a0 = *(const float4*)&A [(size_t)(bm + lr)      * FEATSD + ka];
        float4 a1 = *(const float4*)&A [(size_t)(bm + lr + 32) * FEATSD + ka];
        float4 b0 = *(const float4*)&Bw[(size_t)(bn + lr)      * FEATSD + ka];
        float4 b1 = *(const float4*)&Bw[(size_t)(bn + lr + 32) * FEATSD + ka];
        __syncthreads();
        As[lk+0][lr] = a0.x; As[lk+1][lr] = a0.y; As[lk+2][lr] = a0.z; As[lk+3][lr] = a0.w;
        As[lk+0][lr+32] = a1.x; As[lk+1][lr+32] = a1.y; As[lk+2][lr+32] = a1.z; As[lk+3][lr+32] = a1.w;
        Bs[lk+0][lr] = b0.x; Bs[lk+1][lr] = b0.y; Bs[lk+2][lr] = b0.z; Bs[lk+3][lr] = b0.w;
        Bs[lk+0][lr+32] = b1.x; Bs[lk+1][lr+32] = b1.y; Bs[lk+2][lr+32] = b1.z; Bs[lk+3][lr+32] = b1.w;
        __syncthreads();
        #pragma unroll
        for (int kk = 0; kk < 32; kk++) {
            float4 a = *(const float4*)&As[kk][m0];
            ulonglong2 b = *(const ulonglong2*)&Bs[kk][n0];
            u64 av[4] = { pack2(a.x, a.x), pack2(a.y, a.y),
                          pack2(a.z, a.z), pack2(a.w, a.w) };
            #pragma unroll
            for (int i = 0; i < 4; i++) {
                ffma2(acc2[i][0], av[i], b.x);
                ffma2(acc2[i][1], av[i], b.y);
            }
        }
    }

    #pragma unroll
    for (int i = 0; i < 4; i++) {
        int m = bm + m0 + i;
        #pragma unroll
        for (int j = 0; j < 2; j++) {
            int n = bn + n0 + 2 * j;
            float lo, hi; unpack2(acc2[i][j], lo, hi);
            int idx = m * EMBD + n;
            g_x[idx]     = fmaxf(lo + bias[n],     0.0f);
            g_x[idx + 1] = fmaxf(hi + bias[n + 1], 0.0f);
            g_h[idx] = 0.0f; g_h[idx + 1] = 0.0f;
            g_c[idx] = 0.0f; g_c[idx + 1] = 0.0f;
        }
    }
}

// ================================================================================
// Kernel 2: LSTM gates GEMM (double-buffered FFMA2, proven R12). grid(16,8).
// ================================================================================
__global__ __launch_bounds__(256) void k_gates(const float* __restrict__ Wih,
                                               const float* __restrict__ Whh,
                                               const float* __restrict__ bih,
                                               const float* __restrict__ bhh) {
    __shared__ __align__(16) float As[2][16][132];
    __shared__ __align__(16) float Bs[2][16][132];
    const int tid = threadIdx.x;
    const int bm = blockIdx.y * 128, bn = blockIdx.x * 128;
    const int lr = tid >> 2;
    const int lk = (tid & 3) << 2;
    const int m0 = (tid >> 4) << 2;
    const int n0 = (tid & 15) << 2;
    u64 acc2[8][4] = {};
    float4 ra0, ra1, rb0, rb1;

    ra0 = *(const float4*)&g_x[(size_t)(bm + lr)      * 512 + lk];
    ra1 = *(const float4*)&g_x[(size_t)(bm + lr + 64) * 512 + lk];
    rb0 = *(const float4*)&Wih[(size_t)(bn + lr)      * 512 + lk];
    rb1 = *(const float4*)&Wih[(size_t)(bn + lr + 64) * 512 + lk];
    int buf = 0;
    As[0][lk+0][lr] = ra0.x; As[0][lk+1][lr] = ra0.y; As[0][lk+2][lr] = ra0.z; As[0][lk+3][lr] = ra0.w;
    As[0][lk+0][lr+64] = ra1.x; As[0][lk+1][lr+64] = ra1.y; As[0][lk+2][lr+64] = ra1.z; As[0][lk+3][lr+64] = ra1.w;
    Bs[0][lk+0][lr] = rb0.x; Bs[0][lk+1][lr] = rb0.y; Bs[0][lk+2][lr] = rb0.z; Bs[0][lk+3][lr] = rb0.w;
    Bs[0][lk+0][lr+64] = rb1.x; Bs[0][lk+1][lr+64] = rb1.y; Bs[0][lk+2][lr+64] = rb1.z; Bs[0][lk+3][lr+64] = rb1.w;
    __syncthreads();

    const int S = 64;
    for (int s = 1; s <= S; s++) {
        if (s < S) {
            const int sk = s * 16;
            const float* Ap = (sk < 512) ? g_x : g_h;
            const float* Bp = (sk < 512) ? Wih : Whh;
            const int ka = (sk & 511) + lk;
            ra0 = *(const float4*)&Ap[(size_t)(bm + lr)      * 512 + ka];
            ra1 = *(const float4*)&Ap[(size_t)(bm + lr + 64) * 512 + ka];
            rb0 = *(const float4*)&Bp[(size_t)(bn + lr)      * 512 + ka];
            rb1 = *(const float4*)&Bp[(size_t)(bn + lr + 64) * 512 + ka];
        }
        #pragma unroll
        for (int kk = 0; kk < 16; kk++) {
            float4 a0 = *(const float4*)&As[buf][kk][m0];
            float4 a1 = *(const float4*)&As[buf][kk][m0 + 64];
            ulonglong2 b0 = *(const ulonglong2*)&Bs[buf][kk][n0];
            ulonglong2 b1 = *(const ulonglong2*)&Bs[buf][kk][n0 + 64];
            u64 av[8] = { pack2(a0.x, a0.x), pack2(a0.y, a0.y),
                          pack2(a0.z, a0.z), pack2(a0.w, a0.w),
                          pack2(a1.x, a1.x), pack2(a1.y, a1.y),
                          pack2(a1.z, a1.z), pack2(a1.w, a1.w) };
            u64 bv[4] = { b0.x, b0.y, b1.x, b1.y };
            #pragma unroll
            for (int i = 0; i < 8; i++)
                #pragma unroll
                for (int j = 0; j < 4; j++)
                    ffma2(acc2[i][j], av[i], bv[j]);
        }
        if (s < S) {
            buf ^= 1;
            As[buf][lk+0][lr] = ra0.x; As[buf][lk+1][lr] = ra0.y; As[buf][lk+2][lr] = ra0.z; As[buf][lk+3][lr] = ra0.w;
            As[buf][lk+0][lr+64] = ra1.x; As[buf][lk+1][lr+64] = ra1.y; As[buf][lk+2][lr+64] = ra1.z; As[buf][lk+3][lr+64] = ra1.w;
            Bs[buf][lk+0][lr] = rb0.x; Bs[buf][lk+1][lr] = rb0.y; Bs[buf][lk+2][lr] = rb0.z; Bs[buf][lk+3][lr] = rb0.w;
            Bs[buf][lk+0][lr+64] = rb1.x; Bs[buf][lk+1][lr+64] = rb1.y; Bs[buf][lk+2][lr+64] = rb1.z; Bs[buf][lk+3][lr+64] = rb1.w;
            __syncthreads();
        }
    }

    #pragma unroll
    for (int i = 0; i < 8; i++) {
        int m = bm + m0 + ((i < 4) ? i : 60 + i);
        #pragma unroll
        for (int j = 0; j < 4; j++) {
            int n = bn + n0 + ((j < 2) ? 2*j : 60 + 2*j);
            float lo, hi; unpack2(acc2[i][j], lo, hi);
            g_gates[m * GATES + n]     = lo + bih[n]     + bhh[n];
            g_gates[m * GATES + n + 1] = hi + bih[n + 1] + bhh[n + 1];
        }
    }
}

// ================================================================================
// Kernel 3: logits GEMM + fused argmax, 64x128 tiles (small blocks -> small tail).
// grid(94,16) = 1504 blocks. 256 thr, 4M x 8N per thread, double-buffered BK=16.
// ================================================================================
__global__ __launch_bounds__(256) void k_logits_f(const float* __restrict__ Wout,
                                                  const float* __restrict__ bout) {
    __shared__ __align__(16) float As[2][16][68];
    __shared__ __align__(16) float Bs[2][16][132];
    __shared__ u64 sBest[64];
    const int tid = threadIdx.x;
    const int bm = blockIdx.y * 64, bn = blockIdx.x * 128;
    const int lr = tid >> 2;              // 0..63
    const int lk = (tid & 3) << 2;        // 0,4,8,12
    const int m0 = (tid >> 4) << 2;       // 0..60   (4 rows)
    const int n0 = (tid & 15) << 3;       // 0..120  (8 contiguous cols)
    u64 acc2[4][4] = {};
    float4 ra0, rb0, rb1;
    const float4 z4 = make_float4(0.f, 0.f, 0.f, 0.f);
    const int br0 = bn + lr, br1 = bn + lr + 64;
    const bool v0 = br0 < VOCABO, v1 = br1 < VOCABO;

    if (tid < 64) sBest[tid] = 0ULL;

    ra0 = *(const float4*)&g_h[(size_t)(bm + lr) * 512 + lk];
    rb0 = v0 ? *(const float4*)&Wout[(size_t)br0 * 512 + lk] : z4;
    rb1 = v1 ? *(const float4*)&Wout[(size_t)br1 * 512 + lk] : z4;
    int buf = 0;
    As[0][lk+0][lr] = ra0.x; As[0][lk+1][lr] = ra0.y; As[0][lk+2][lr] = ra0.z; As[0][lk+3][lr] = ra0.w;
    Bs[0][lk+0][lr] = rb0.x; Bs[0][lk+1][lr] = rb0.y; Bs[0][lk+2][lr] = rb0.z; Bs[0][lk+3][lr] = rb0.w;
    Bs[0][lk+0][lr+64] = rb1.x; Bs[0][lk+1][lr+64] = rb1.y; Bs[0][lk+2][lr+64] = rb1.z; Bs[0][lk+3][lr+64] = rb1.w;
    __syncthreads();

    const int S = 32;                     // K = 512, BK = 16
    for (int s = 1; s <= S; s++) {
        if (s < S) {
            const int ka = s * 16 + lk;
            ra0 = *(const float4*)&g_h[(size_t)(bm + lr) * 512 + ka];
            rb0 = v0 ? *(const float4*)&Wout[(size_t)br0 * 512 + ka] : z4;
            rb1 = v1 ? *(const float4*)&Wout[(size_t)br1 * 512 + ka] : z4;
        }
        #pragma unroll
        for (int kk = 0; kk < 16; kk++) {
            float4 a = *(const float4*)&As[buf][kk][m0];
            ulonglong2 b0 = *(const ulonglong2*)&Bs[buf][kk][n0];
            ulonglong2 b1 = *(const ulonglong2*)&Bs[buf][kk][n0 + 4];
            u64 av[4] = { pack2(a.x, a.x), pack2(a.y, a.y),
                          pack2(a.z, a.z), pack2(a.w, a.w) };
            u64 bv[4] = { b0.x, b0.y, b1.x, b1.y };
            #pragma unroll
            for (int i = 0; i < 4; i++)
                #pragma unroll
                for (int j = 0; j < 4; j++)
                    ffma2(acc2[i][j], av[i], bv[j]);
        }
        if (s < S) {
            buf ^= 1;
            As[buf][lk+0][lr] = ra0.x; As[buf][lk+1][lr] = ra0.y; As[buf][lk+2][lr] = ra0.z; As[buf][lk+3][lr] = ra0.w;
            Bs[buf][lk+0][lr] = rb0.x; Bs[buf][lk+1][lr] = rb0.y; Bs[buf][lk+2][lr] = rb0.z; Bs[buf][lk+3][lr] = rb0.w;
            Bs[buf][lk+0][lr+64] = rb1.x; Bs[buf][lk+1][lr+64] = rb1.y; Bs[buf][lk+2][lr+64] = rb1.z; Bs[buf][lk+3][lr+64] = rb1.w;
            __syncthreads();
        }
    }
    __syncthreads();   // sBest init visible + last compute done

    // ---- fused argmax epilogue: 8 contiguous cols n0..n0+7 ----------------------
    #pragma unroll
    for (int i = 0; i < 4; i++) {
        u64 best = 0ULL;
        #pragma unroll
        for (int j = 0; j < 4; j++) {
            int n = bn + n0 + 2 * j;
            float lo, hi; unpack2(acc2[i][j], lo, hi);
            if (n < VOCABO) {
                u64 key = amax_key(lo + bout[n], n);
                if (key > best) best = key;
            }
            if (n + 1 < VOCABO) {
                u64 key = amax_key(hi + bout[n + 1], n + 1);
                if (key > best) best = key;
            }
        }
        atomicMax(&sBest[m0 + i], best);
    }
    __syncthreads();
    if (tid < 64) atomicMax(&g_amax[bm + tid], sBest[tid]);
}

// -------- Kernel 4: LSTM pointwise + argmax accumulator reset -------------------
__global__ void k_point() {
    int idx = blockIdx.x * blockDim.x + threadIdx.x;
    int b = idx >> 9, n = idx & 511;
    const float* g = g_gates + b * GATES;
    float ig = sigm_f(g[n]);
    float fg = sigm_f(g[512 + n]);
    float gg = tanh_f(g[1024 + n]);
    float og = sigm_f(g[1536 + n]);
    float c = fg * g_c[idx] + ig * gg;
    g_c[idx] = c;
    g_h[idx] = og * tanh_f(c);
    if (idx < BATCH) g_amax[idx] = 0ULL;
}

// -------- Kernel 5: embedding gather + decode previous step's argmax ------------
__global__ void k_embed(const float* __restrict__ emb, float* __restrict__ out,
                        int t) {
    int b = blockIdx.x;
    int w;
    if (t == 0) {
        w = 1;                                   // START token
    } else {
        u64 key = g_amax[b];                     // from logits of step t-1
        int idx = (int)(0xFFFFFFFFu - (unsigned)(key & 0xFFFFFFFFull));
        if (threadIdx.x == 0) out[b * TSTEPS + (t - 1)] = (float)idx;
        w = idx + 2;
    }
    const float4* src = (const float4*)(emb + (size_t)w * EMBD);
    float4* dst = (float4*)(g_x + (size_t)b * EMBD);
    dst[threadIdx.x] = src[threadIdx.x];
}

// -------- Kernel 6: final decode for the last step ------------------------------
__global__ void k_finish(float* __restrict__ out, int t) {
    int b = blockIdx.x * blockDim.x + threadIdx.x;
    if (b < BATCH) {
        u64 key = g_amax[b];
        int idx = (int)(0xFFFFFFFFu - (unsigned)(key & 0xFFFFFFFFull));
        out[b * TSTEPS + t] = (float)idx;
    }
}

// ================================================================================
extern "C" void kernel_launch(void* const* d_in, const int* in_sizes, int n_in,
                              void* d_out, int out_size) {
    const float *img = 0, *W_feats = 0, *b_feats = 0, *W_ih = 0, *W_hh = 0,
                *b_ih = 0, *b_hh = 0, *emb = 0, *W_out = 0, *b_out = 0;
    for (int i = 0; i < n_in; i++) {
        const float* p = (const float*)d_in[i];
        switch (in_sizes[i]) {
            case 4194304: img = p; break;
            case 2097152: W_feats = p; break;
            case 512:     b_feats = p; break;
            case 1048576: if (!W_ih) W_ih = p; else W_hh = p; break;
            case 2048:    if (!b_ih) b_ih = p; else b_hh = p; break;
            case 6144000: emb = p; break;
            case 6142976: W_out = p; break;
            case 11998:   b_out = p; break;
            default: break;
        }
    }
    if (!img || !W_feats || !b_feats || !W_ih || !W_hh || !b_ih || !b_hh ||
        !emb || !W_out || !b_out) {
        img     = (const float*)d_in[0];
        W_feats = (const float*)d_in[1];
        b_feats = (const float*)d_in[2];
        W_ih    = (const float*)d_in[3];
        W_hh    = (const float*)d_in[4];
        b_ih    = (const float*)d_in[5];
        b_hh    = (const float*)d_in[6];
        emb     = (const float*)d_in[7];
        W_out   = (const float*)d_in[8];
        b_out   = (const float*)d_in[9];
    }
    float* out = (float*)d_out;

    k_prime <<<dim3(8, 16), 256>>>(img, W_feats, b_feats);
    k_gates <<<dim3(16, 8), 256>>>(W_ih, W_hh, b_ih, b_hh);
    k_point <<<2048, 256>>>();

    for (int t = 0; t < TSTEPS; t++) {
        k_embed    <<<1024, 128>>>(emb, out, t);     // also emits token t-1
        k_gates    <<<dim3(16, 8), 256>>>(W_ih, W_hh, b_ih, b_hh);
        k_point    <<<2048, 256>>>();
        k_logits_f <<<dim3(94, 16), 256>>>(W_out, b_out);
    }
    k_finish <<<4, 256>>>(out, TSTEPS - 1);          // emit final token
}

// round 14
// speedup vs baseline: 1.2673x; 1.2673x over previous
#include <cuda_runtime.h>
#include <math.h>
#include <cstdint>

#define BATCH   1024
#define EMBD    512
#define RNND    512
#define GATES   2048
#define VOCABO  11998
#define FEATSD  4096
#define TSTEPS  15

typedef unsigned long long u64;

// ---------------- scratch (__device__ globals; no runtime allocation) ----------
__device__ float g_x[BATCH * EMBD];
__device__ float g_h[BATCH * RNND];
__device__ float g_c[BATCH * RNND];
__device__ float g_gates[BATCH * GATES];
__device__ u64   g_amax[BATCH];

// ---------------- packed f32x2 helpers ------------------------------------------
__device__ __forceinline__ u64 pack2(float lo, float hi) {
    u64 r; asm("mov.b64 %0, {%1, %2};" : "=l"(r) : "f"(lo), "f"(hi)); return r;
}
__device__ __forceinline__ void unpack2(u64 v, float& lo, float& hi) {
    asm("mov.b64 {%0, %1}, %2;" : "=f"(lo), "=f"(hi) : "l"(v));
}
__device__ __forceinline__ void ffma2(u64& d, u64 a, u64 b) {
    asm("fma.rn.f32x2 %0, %1, %2, %0;" : "+l"(d) : "l"(a), "l"(b));
}

// ---------------- activations ---------------------------------------------------
__device__ __forceinline__ float sigm_f(float x) { return 1.0f / (1.0f + expf(-x)); }
__device__ __forceinline__ float tanh_f(float x) {
    float e = expf(-2.0f * fabsf(x));
    float t = (1.0f - e) / (1.0f + e);
    return copysignf(t, x);
}
__device__ __forceinline__ u64 amax_key(float v, int n) {
    unsigned u = __float_as_uint(v);
    u = (u & 0x80000000u) ? ~u : (u | 0x80000000u);
    return ((u64)u << 32) | (u64)(0xFFFFFFFFu - (unsigned)n);
}

// ================================================================================
// Kernel 1: g_x = relu(img[1024,4096] @ W_feats^T + b); zero h, c. (proven R12)
// ================================================================================
__global__ __launch_bounds__(256) void k_prime(const float* __restrict__ A,
                                               const float* __restrict__ Bw,
                                               const float* __restrict__ bias) {
    __shared__ __align__(16) float As[32][68];
    __shared__ __align__(16) float Bs[32][68];
    const int tid = threadIdx.x;
    const int bm = blockIdx.y * 64, bn = blockIdx.x * 64;
    const int lr = tid >> 3, lk = (tid & 7) << 2;
    const int m0 = (tid >> 4) << 2, n0 = (tid & 15) << 2;
    u64 acc2[4][2] = {};

    for (int s = 0; s < FEATSD / 32; s++) {
        const int ka = s * 32 + lk;
        float4 a0 = *(const float4*)&A [(size_t)(bm + lr)      * FEATSD + ka];
        float4 a1 = *(const float4*)&A [(size_t)(bm + lr + 32) * FEATSD + ka];
        float4 b0 = *(const float4*)&Bw[(size_t)(bn + lr)      * FEATSD + ka];
        float4 b1 = *(const float4*)&Bw[(size_t)(bn + lr + 32) * FEATSD + ka];
        __syncthreads();
        As[lk+0][lr] = a0.x; As[lk+1][lr] = a0.y; As[lk+2][lr] = a0.z; As[lk+3][lr] = a0.w;
        As[lk+0][lr+32] = a1.x; As[lk+1][lr+32] = a1.y; As[lk+2][lr+32] = a1.z; As[lk+3][lr+32] = a1.w;
        Bs[lk+0][lr] = b0.x; Bs[lk+1][lr] = b0.y; Bs[lk+2][lr] = b0.z; Bs[lk+3][lr] = b0.w;
        Bs[lk+0][lr+32] = b1.x; Bs[lk+1][lr+32] = b1.y; Bs[lk+2][lr+32] = b1.z; Bs[lk+3][lr+32] = b1.w;
        __syncthreads();
        #pragma unroll
        for (int kk = 0; kk < 32; kk++) {
            float4 a = *(const float4*)&As[kk][m0];
            ulonglong2 b = *(const ulonglong2*)&Bs[kk][n0];
            u64 av[4] = { pack2(a.x, a.x), pack2(a.y, a.y),
                          pack2(a.z, a.z), pack2(a.w, a.w) };
            #pragma unroll
            for (int i = 0; i < 4; i++) {
                ffma2(acc2[i][0], av[i], b.x);
                ffma2(acc2[i][1], av[i], b.y);
            }
        }
    }

    #pragma unroll
    for (int i = 0; i < 4; i++) {
        int m = bm + m0 + i;
        #pragma unroll
        for (int j = 0; j < 2; j++) {
            int n = bn + n0 + 2 * j;
            float lo, hi; unpack2(acc2[i][j], lo, hi);
            int idx = m * EMBD + n;
            g_x[idx]     = fmaxf(lo + bias[n],     0.0f);
            g_x[idx + 1] = fmaxf(hi + bias[n + 1], 0.0f);
            g_h[idx] = 0.0f; g_h[idx + 1] = 0.0f;
            g_c[idx] = 0.0f; g_c[idx + 1] = 0.0f;
        }
    }
}

// ================================================================================
// Kernel 2: LSTM gates GEMM (double-buffered FFMA2, proven R12). grid(16,8).
// ================================================================================
__global__ __launch_bounds__(256) void k_gates(const float* __restrict__ Wih,
                                               const float* __restrict__ Whh,
                                               const float* __restrict__ bih,
                                               const float* __restrict__ bhh) {
    __shared__ __align__(16) float As[2][16][132];
    __shared__ __align__(16) float Bs[2][16][132];
    const int tid = threadIdx.x;
    const int bm = blockIdx.y * 128, bn = blockIdx.x * 128;
    const int lr = tid >> 2;
    const int lk = (tid & 3) << 2;
    const int m0 = (tid >> 4) << 2;
    const int n0 = (tid & 15) << 2;
    u64 acc2[8][4] = {};
    float4 ra0, ra1, rb0, rb1;

    ra0 = *(const float4*)&g_x[(size_t)(bm + lr)      * 512 + lk];
    ra1 = *(const float4*)&g_x[(size_t)(bm + lr + 64) * 512 + lk];
    rb0 = *(const float4*)&Wih[(size_t)(bn + lr)      * 512 + lk];
    rb1 = *(const float4*)&Wih[(size_t)(bn + lr + 64) * 512 + lk];
    int buf = 0;
    As[0][lk+0][lr] = ra0.x; As[0][lk+1][lr] = ra0.y; As[0][lk+2][lr] = ra0.z; As[0][lk+3][lr] = ra0.w;
    As[0][lk+0][lr+64] = ra1.x; As[0][lk+1][lr+64] = ra1.y; As[0][lk+2][lr+64] = ra1.z; As[0][lk+3][lr+64] = ra1.w;
    Bs[0][lk+0][lr] = rb0.x; Bs[0][lk+1][lr] = rb0.y; Bs[0][lk+2][lr] = rb0.z; Bs[0][lk+3][lr] = rb0.w;
    Bs[0][lk+0][lr+64] = rb1.x; Bs[0][lk+1][lr+64] = rb1.y; Bs[0][lk+2][lr+64] = rb1.z; Bs[0][lk+3][lr+64] = rb1.w;
    __syncthreads();

    const int S = 64;
    for (int s = 1; s <= S; s++) {
        if (s < S) {
            const int sk = s * 16;
            const float* Ap = (sk < 512) ? g_x : g_h;
            const float* Bp = (sk < 512) ? Wih : Whh;
            const int ka = (sk & 511) + lk;
            ra0 = *(const float4*)&Ap[(size_t)(bm + lr)      * 512 + ka];
            ra1 = *(const float4*)&Ap[(size_t)(bm + lr + 64) * 512 + ka];
            rb0 = *(const float4*)&Bp[(size_t)(bn + lr)      * 512 + ka];
            rb1 = *(const float4*)&Bp[(size_t)(bn + lr + 64) * 512 + ka];
        }
        #pragma unroll
        for (int kk = 0; kk < 16; kk++) {
            float4 a0 = *(const float4*)&As[buf][kk][m0];
            float4 a1 = *(const float4*)&As[buf][kk][m0 + 64];
            ulonglong2 b0 = *(const ulonglong2*)&Bs[buf][kk][n0];
            ulonglong2 b1 = *(const ulonglong2*)&Bs[buf][kk][n0 + 64];
            u64 av[8] = { pack2(a0.x, a0.x), pack2(a0.y, a0.y),
                          pack2(a0.z, a0.z), pack2(a0.w, a0.w),
                          pack2(a1.x, a1.x), pack2(a1.y, a1.y),
                          pack2(a1.z, a1.z), pack2(a1.w, a1.w) };
            u64 bv[4] = { b0.x, b0.y, b1.x, b1.y };
            #pragma unroll
            for (int i = 0; i < 8; i++)
                #pragma unroll
                for (int j = 0; j < 4; j++)
                    ffma2(acc2[i][j], av[i], bv[j]);
        }
        if (s < S) {
            buf ^= 1;
            As[buf][lk+0][lr] = ra0.x; As[buf][lk+1][lr] = ra0.y; As[buf][lk+2][lr] = ra0.z; As[buf][lk+3][lr] = ra0.w;
            As[buf][lk+0][lr+64] = ra1.x; As[buf][lk+1][lr+64] = ra1.y; As[buf][lk+2][lr+64] = ra1.z; As[buf][lk+3][lr+64] = ra1.w;
            Bs[buf][lk+0][lr] = rb0.x; Bs[buf][lk+1][lr] = rb0.y; Bs[buf][lk+2][lr] = rb0.z; Bs[buf][lk+3][lr] = rb0.w;
            Bs[buf][lk+0][lr+64] = rb1.x; Bs[buf][lk+1][lr+64] = rb1.y; Bs[buf][lk+2][lr+64] = rb1.z; Bs[buf][lk+3][lr+64] = rb1.w;
            __syncthreads();
        }
    }

    #pragma unroll
    for (int i = 0; i < 8; i++) {
        int m = bm + m0 + ((i < 4) ? i : 60 + i);
        #pragma unroll
        for (int j = 0; j < 4; j++) {
            int n = bn + n0 + ((j < 2) ? 2*j : 60 + 2*j);
            float lo, hi; unpack2(acc2[i][j], lo, hi);
            g_gates[m * GATES + n]     = lo + bih[n]     + bhh[n];
            g_gates[m * GATES + n + 1] = hi + bih[n + 1] + bhh[n + 1];
        }
    }
}

// ================================================================================
// Kernel 3: logits GEMM + fused argmax. 128M x 64N tile, 128 threads, 8x8/thread
// (SAME per-thread density as R12 — the proven-fast inner loop), double-buffered
// BK=16. grid(188, 8) = 1504 small blocks -> small straggler tail.
// ================================================================================
__global__ __launch_bounds__(128) void k_logits_f(const float* __restrict__ Wout,
                                                  const float* __restrict__ bout) {
    __shared__ __align__(16) float As[2][16][132];   // 128 batch rows (+pad)
    __shared__ __align__(16) float Bs[2][16][68];    // 64 vocab rows (+pad)
    __shared__ u64 sBest[128];
    const int tid = threadIdx.x;
    const int bm = blockIdx.y * 128;       // batch rows
    const int bn = blockIdx.x * 64;        // vocab rows
    const int m0 = (tid >> 3) << 3;        // 0..120 (8 contiguous rows)
    const int n0 = (tid & 7) << 3;         // 0..56  (8 contiguous cols)
    // A load map: chunk = tid + 128u -> row=chunk>>2, col4=(chunk&3)<<2 (coalesced)
    // B load map: row = tid>>1, col half = (tid&1)*8 (coalesced 64B per row)
    const int brow = tid >> 1;
    const int bc   = (tid & 1) << 3;
    const int bglob = bn + brow;
    const bool bok = bglob < VOCABO;
    u64 acc2[8][4] = {};
    float4 ra[4], rb0, rb1;
    const float4 z4 = make_float4(0.f, 0.f, 0.f, 0.f);

    sBest[tid] = 0ULL;

    #pragma unroll
    for (int u = 0; u < 4; u++) {
        int chunk = tid + (u << 7);
        int row = chunk >> 2, c4 = (chunk & 3) << 2;
        ra[u] = *(const float4*)&g_h[(size_t)(bm + row) * 512 + c4];
    }
    rb0 = bok ? *(const float4*)&Wout[(size_t)bglob * 512 + bc]     : z4;
    rb1 = bok ? *(const float4*)&Wout[(size_t)bglob * 512 + bc + 4] : z4;
    int buf = 0;
    #pragma unroll
    for (int u = 0; u < 4; u++) {
        int chunk = tid + (u << 7);
        int row = chunk >> 2, c4 = (chunk & 3) << 2;
        As[0][c4+0][row] = ra[u].x; As[0][c4+1][row] = ra[u].y;
        As[0][c4+2][row] = ra[u].z; As[0][c4+3][row] = ra[u].w;
    }
    Bs[0][bc+0][brow] = rb0.x; Bs[0][bc+1][brow] = rb0.y;
    Bs[0][bc+2][brow] = rb0.z; Bs[0][bc+3][brow] = rb0.w;
    Bs[0][bc+4][brow] = rb1.x; Bs[0][bc+5][brow] = rb1.y;
    Bs[0][bc+6][brow] = rb1.z; Bs[0][bc+7][brow] = rb1.w;
    __syncthreads();

    const int S = 32;                      // K = 512, BK = 16
    for (int s = 1; s <= S; s++) {
        if (s < S) {
            const int sk = s * 16;
            #pragma unroll
            for (int u = 0; u < 4; u++) {
                int chunk = tid + (u << 7);
                int row = chunk >> 2, c4 = (chunk & 3) << 2;
                ra[u] = *(const float4*)&g_h[(size_t)(bm + row) * 512 + sk + c4];
            }
            rb0 = bok ? *(const float4*)&Wout[(size_t)bglob * 512 + sk + bc]     : z4;
            rb1 = bok ? *(const float4*)&Wout[(size_t)bglob * 512 + sk + bc + 4] : z4;
        }
        #pragma unroll
        for (int kk = 0; kk < 16; kk++) {
            float4 a0 = *(const float4*)&As[buf][kk][m0];
            float4 a1 = *(const float4*)&As[buf][kk][m0 + 4];
            ulonglong2 b0 = *(const ulonglong2*)&Bs[buf][kk][n0];
            ulonglong2 b1 = *(const ulonglong2*)&Bs[buf][kk][n0 + 4];
            u64 av[8] = { pack2(a0.x, a0.x), pack2(a0.y, a0.y),
                          pack2(a0.z, a0.z), pack2(a0.w, a0.w),
                          pack2(a1.x, a1.x), pack2(a1.y, a1.y),
                          pack2(a1.z, a1.z), pack2(a1.w, a1.w) };
            u64 bv[4] = { b0.x, b0.y, b1.x, b1.y };
            #pragma unroll
            for (int i = 0; i < 8; i++)
                #pragma unroll
                for (int j = 0; j < 4; j++)
                    ffma2(acc2[i][j], av[i], bv[j]);
        }
        if (s < S) {
            buf ^= 1;
            #pragma unroll
            for (int u = 0; u < 4; u++) {
                int chunk = tid + (u << 7);
                int row = chunk >> 2, c4 = (chunk & 3) << 2;
                As[buf][c4+0][row] = ra[u].x; As[buf][c4+1][row] = ra[u].y;
                As[buf][c4+2][row] = ra[u].z; As[buf][c4+3][row] = ra[u].w;
            }
            Bs[buf][bc+0][brow] = rb0.x; Bs[buf][bc+1][brow] = rb0.y;
            Bs[buf][bc+2][brow] = rb0.z; Bs[buf][bc+3][brow] = rb0.w;
            Bs[buf][bc+4][brow] = rb1.x; Bs[buf][bc+5][brow] = rb1.y;
            Bs[buf][bc+6][brow] = rb1.z; Bs[buf][bc+7][brow] = rb1.w;
            __syncthreads();
        }
    }
    __syncthreads();   // sBest init visible + last compute complete

    // ---- fused argmax epilogue: rows m0..m0+7, cols bn+n0..bn+n0+7 --------------
    #pragma unroll
    for (int i = 0; i < 8; i++) {
        u64 best = 0ULL;
        #pragma unroll
        for (int j = 0; j < 4; j++) {
            int n = bn + n0 + 2 * j;
            float lo, hi; unpack2(acc2[i][j], lo, hi);
            if (n < VOCABO) {
                u64 key = amax_key(lo + bout[n], n);
                if (key > best) best = key;
            }
            if (n + 1 < VOCABO) {
                u64 key = amax_key(hi + bout[n + 1], n + 1);
                if (key > best) best = key;
            }
        }
        atomicMax(&sBest[m0 + i], best);
    }
    __syncthreads();
    atomicMax(&g_amax[bm + tid], sBest[tid]);
}

// -------- Kernel 4: LSTM pointwise + argmax accumulator reset -------------------
__global__ void k_point() {
    int idx = blockIdx.x * blockDim.x + threadIdx.x;
    int b = idx >> 9, n = idx & 511;
    const float* g = g_gates + b * GATES;
    float ig = sigm_f(g[n]);
    float fg = sigm_f(g[512 + n]);
    float gg = tanh_f(g[1024 + n]);
    float og = sigm_f(g[1536 + n]);
    float c = fg * g_c[idx] + ig * gg;
    g_c[idx] = c;
    g_h[idx] = og * tanh_f(c);
    if (idx < BATCH) g_amax[idx] = 0ULL;
}

// -------- Kernel 5: embedding gather + decode previous step's argmax ------------
__global__ void k_embed(const float* __restrict__ emb, float* __restrict__ out,
                        int t) {
    int b = blockIdx.x;
    int w;
    if (t == 0) {
        w = 1;                                   // START token
    } else {
        u64 key = g_amax[b];                     // from logits of step t-1
        int idx = (int)(0xFFFFFFFFu - (unsigned)(key & 0xFFFFFFFFull));
        if (threadIdx.x == 0) out[b * TSTEPS + (t - 1)] = (float)idx;
        w = idx + 2;
    }
    const float4* src = (const float4*)(emb + (size_t)w * EMBD);
    float4* dst = (float4*)(g_x + (size_t)b * EMBD);
    dst[threadIdx.x] = src[threadIdx.x];
}

// -------- Kernel 6: final decode for the last step ------------------------------
__global__ void k_finish(float* __restrict__ out, int t) {
    int b = blockIdx.x * blockDim.x + threadIdx.x;
    if (b < BATCH) {
        u64 key = g_amax[b];
        int idx = (int)(0xFFFFFFFFu - (unsigned)(key & 0xFFFFFFFFull));
        out[b * TSTEPS + t] = (float)idx;
    }
}

// ================================================================================
extern "C" void kernel_launch(void* const* d_in, const int* in_sizes, int n_in,
                              void* d_out, int out_size) {
    const float *img = 0, *W_feats = 0, *b_feats = 0, *W_ih = 0, *W_hh = 0,
                *b_ih = 0, *b_hh = 0, *emb = 0, *W_out = 0, *b_out = 0;
    for (int i = 0; i < n_in; i++) {
        const float* p = (const float*)d_in[i];
        switch (in_sizes[i]) {
            case 4194304: img = p; break;
            case 2097152: W_feats = p; break;
            case 512:     b_feats = p; break;
            case 1048576: if (!W_ih) W_ih = p; else W_hh = p; break;
            case 2048:    if (!b_ih) b_ih = p; else b_hh = p; break;
            case 6144000: emb = p; break;
            case 6142976: W_out = p; break;
            case 11998:   b_out = p; break;
            default: break;
        }
    }
    if (!img || !W_feats || !b_feats || !W_ih || !W_hh || !b_ih || !b_hh ||
        !emb || !W_out || !b_out) {
        img     = (const float*)d_in[0];
        W_feats = (const float*)d_in[1];
        b_feats = (const float*)d_in[2];
        W_ih    = (const float*)d_in[3];
        W_hh    = (const float*)d_in[4];
        b_ih    = (const float*)d_in[5];
        b_hh    = (const float*)d_in[6];
        emb     = (const float*)d_in[7];
        W_out   = (const float*)d_in[8];
        b_out   = (const float*)d_in[9];
    }
    float* out = (float*)d_out;

    k_prime <<<dim3(8, 16), 256>>>(img, W_feats, b_feats);
    k_gates <<<dim3(16, 8), 256>>>(W_ih, W_hh, b_ih, b_hh);
    k_point <<<2048, 256>>>();

    for (int t = 0; t < TSTEPS; t++) {
        k_embed    <<<1024, 128>>>(emb, out, t);     // also emits token t-1
        k_gates    <<<dim3(16, 8), 256>>>(W_ih, W_hh, b_ih, b_hh);
        k_point    <<<2048, 256>>>();
        k_logits_f <<<dim3(188, 8), 128>>>(W_out, b_out);
    }
    k_finish <<<4, 256>>>(out, TSTEPS - 1);          // emit final token
}

// round 15
// speedup vs baseline: 1.7078x; 1.3476x over previous
#include <cuda_runtime.h>
#include <math.h>
#include <cstdint>

#define BATCH   1024
#define EMBD    512
#define RNND    512
#define GATES   2048
#define VOCABO  11998
#define FEATSD  4096
#define TSTEPS  15

typedef unsigned long long u64;

// ---------------- scratch (__device__ globals; no runtime allocation) ----------
__device__ float g_x[BATCH * EMBD];      // priming input only
__device__ float g_h[BATCH * RNND];
__device__ float g_c[BATCH * RNND];
__device__ float g_gates[BATCH * GATES];
__device__ u64   g_amax[BATCH];

// ---------------- packed f32x2 helpers ------------------------------------------
__device__ __forceinline__ u64 pack2(float lo, float hi) {
    u64 r; asm("mov.b64 %0, {%1, %2};" : "=l"(r) : "f"(lo), "f"(hi)); return r;
}
__device__ __forceinline__ void unpack2(u64 v, float& lo, float& hi) {
    asm("mov.b64 {%0, %1}, %2;" : "=f"(lo), "=f"(hi) : "l"(v));
}
__device__ __forceinline__ void ffma2(u64& d, u64 a, u64 b) {
    asm("fma.rn.f32x2 %0, %1, %2, %0;" : "+l"(d) : "l"(a), "l"(b));
}

// ---------------- activations / argmax keys -------------------------------------
__device__ __forceinline__ float sigm_f(float x) { return 1.0f / (1.0f + expf(-x)); }
__device__ __forceinline__ float tanh_f(float x) {
    float e = expf(-2.0f * fabsf(x));
    float t = (1.0f - e) / (1.0f + e);
    return copysignf(t, x);
}
__device__ __forceinline__ u64 amax_key(float v, int n) {
    unsigned u = __float_as_uint(v);
    u = (u & 0x80000000u) ? ~u : (u | 0x80000000u);
    return ((u64)u << 32) | (u64)(0xFFFFFFFFu - (unsigned)n);
}
__device__ __forceinline__ int amax_idx(u64 key) {
    return (int)(0xFFFFFFFFu - (unsigned)(key & 0xFFFFFFFFull));
}

// ================================================================================
// Kernel 1: g_x = relu(img[1024,4096] @ W_feats^T + b); zero h, c. (proven R12)
// ================================================================================
__global__ __launch_bounds__(256) void k_prime(const float* __restrict__ A,
                                               const float* __restrict__ Bw,
                                               const float* __restrict__ bias) {
    __shared__ __align__(16) float As[32][68];
    __shared__ __align__(16) float Bs[32][68];
    const int tid = threadIdx.x;
    const int bm = blockIdx.y * 64, bn = blockIdx.x * 64;
    const int lr = tid >> 3, lk = (tid & 7) << 2;
    const int m0 = (tid >> 4) << 2, n0 = (tid & 15) << 2;
    u64 acc2[4][2] = {};

    for (int s = 0; s < FEATSD / 32; s++) {
        const int ka = s * 32 + lk;
        float4 a0 = *(const float4*)&A [(size_t)(bm + lr)      * FEATSD + ka];
        float4 a1 = *(const float4*)&A [(size_t)(bm + lr + 32) * FEATSD + ka];
        float4 b0 = *(const float4*)&Bw[(size_t)(bn + lr)      * FEATSD + ka];
        float4 b1 = *(const float4*)&Bw[(size_t)(bn + lr + 32) * FEATSD + ka];
        __syncthreads();
        As[lk+0][lr] = a0.x; As[lk+1][lr] = a0.y; As[lk+2][lr] = a0.z; As[lk+3][lr] = a0.w;
        As[lk+0][lr+32] = a1.x; As[lk+1][lr+32] = a1.y; As[lk+2][lr+32] = a1.z; As[lk+3][lr+32] = a1.w;
        Bs[lk+0][lr] = b0.x; Bs[lk+1][lr] = b0.y; Bs[lk+2][lr] = b0.z; Bs[lk+3][lr] = b0.w;
        Bs[lk+0][lr+32] = b1.x; Bs[lk+1][lr+32] = b1.y; Bs[lk+2][lr+32] = b1.z; Bs[lk+3][lr+32] = b1.w;
        __syncthreads();
        #pragma unroll
        for (int kk = 0; kk < 32; kk++) {
            float4 a = *(const float4*)&As[kk][m0];
            ulonglong2 b = *(const ulonglong2*)&Bs[kk][n0];
            u64 av[4] = { pack2(a.x, a.x), pack2(a.y, a.y),
                          pack2(a.z, a.z), pack2(a.w, a.w) };
            #pragma unroll
            for (int i = 0; i < 4; i++) {
                ffma2(acc2[i][0], av[i], b.x);
                ffma2(acc2[i][1], av[i], b.y);
            }
        }
    }

    #pragma unroll
    for (int i = 0; i < 4; i++) {
        int m = bm + m0 + i;
        #pragma unroll
        for (int j = 0; j < 2; j++) {
            int n = bn + n0 + 2 * j;
            float lo, hi; unpack2(acc2[i][j], lo, hi);
            int idx = m * EMBD + n;
            g_x[idx]     = fmaxf(lo + bias[n],     0.0f);
            g_x[idx + 1] = fmaxf(hi + bias[n + 1], 0.0f);
            g_h[idx] = 0.0f; g_h[idx + 1] = 0.0f;
            g_c[idx] = 0.0f; g_c[idx + 1] = 0.0f;
        }
    }
}

// ================================================================================
// Kernel 2: LSTM gates GEMM (R12 inner loop, byte-identical math).
// A-source for K<512: use_emb ? emb[word(amax)] gather : g_x (priming).
// grid(16,8), 256 thr, 128x128 tile, 8x8/thread, double-buffered BK=16.
// ================================================================================
__global__ __launch_bounds__(256) void k_gates(const float* __restrict__ Wih,
                                               const float* __restrict__ Whh,
                                               const float* __restrict__ bih,
                                               const float* __restrict__ bhh,
                                               const float* __restrict__ emb,
                                               int t, int use_emb) {
    __shared__ __align__(16) float As[2][16][132];
    __shared__ __align__(16) float Bs[2][16][132];
    const int tid = threadIdx.x;
    const int bm = blockIdx.y * 128, bn = blockIdx.x * 128;
    const int lr = tid >> 2;
    const int lk = (tid & 3) << 2;
    const int m0 = (tid >> 4) << 2;
    const int n0 = (tid & 15) << 2;
    u64 acc2[8][4] = {};
    float4 ra0, ra1, rb0, rb1;

    // resolve the two A-row base pointers for the K<512 half
    const float* arow0;
    const float* arow1;
    if (use_emb) {
        int w0 = 1, w1 = 1;
        if (t > 0) {
            w0 = amax_idx(g_amax[bm + lr])      + 2;   // prev-step token
            w1 = amax_idx(g_amax[bm + lr + 64]) + 2;
        }
        arow0 = emb + (size_t)w0 * EMBD;
        arow1 = emb + (size_t)w1 * EMBD;
    } else {
        arow0 = g_x + (size_t)(bm + lr)      * EMBD;
        arow1 = g_x + (size_t)(bm + lr + 64) * EMBD;
    }

    ra0 = *(const float4*)&arow0[lk];
    ra1 = *(const float4*)&arow1[lk];
    rb0 = *(const float4*)&Wih[(size_t)(bn + lr)      * 512 + lk];
    rb1 = *(const float4*)&Wih[(size_t)(bn + lr + 64) * 512 + lk];
    int buf = 0;
    As[0][lk+0][lr] = ra0.x; As[0][lk+1][lr] = ra0.y; As[0][lk+2][lr] = ra0.z; As[0][lk+3][lr] = ra0.w;
    As[0][lk+0][lr+64] = ra1.x; As[0][lk+1][lr+64] = ra1.y; As[0][lk+2][lr+64] = ra1.z; As[0][lk+3][lr+64] = ra1.w;
    Bs[0][lk+0][lr] = rb0.x; Bs[0][lk+1][lr] = rb0.y; Bs[0][lk+2][lr] = rb0.z; Bs[0][lk+3][lr] = rb0.w;
    Bs[0][lk+0][lr+64] = rb1.x; Bs[0][lk+1][lr+64] = rb1.y; Bs[0][lk+2][lr+64] = rb1.z; Bs[0][lk+3][lr+64] = rb1.w;
    __syncthreads();

    const int S = 64;                     // virtual K = 1024, BK = 16
    for (int s = 1; s <= S; s++) {
        if (s < S) {
            const int sk = s * 16;
            const int ka = (sk & 511) + lk;
            if (sk < 512) {
                ra0 = *(const float4*)&arow0[ka];
                ra1 = *(const float4*)&arow1[ka];
                rb0 = *(const float4*)&Wih[(size_t)(bn + lr)      * 512 + ka];
                rb1 = *(const float4*)&Wih[(size_t)(bn + lr + 64) * 512 + ka];
            } else {
                ra0 = *(const float4*)&g_h[(size_t)(bm + lr)      * 512 + ka];
                ra1 = *(const float4*)&g_h[(size_t)(bm + lr + 64) * 512 + ka];
                rb0 = *(const float4*)&Whh[(size_t)(bn + lr)      * 512 + ka];
                rb1 = *(const float4*)&Whh[(size_t)(bn + lr + 64) * 512 + ka];
            }
        }
        #pragma unroll
        for (int kk = 0; kk < 16; kk++) {
            float4 a0 = *(const float4*)&As[buf][kk][m0];
            float4 a1 = *(const float4*)&As[buf][kk][m0 + 64];
            ulonglong2 b0 = *(const ulonglong2*)&Bs[buf][kk][n0];
            ulonglong2 b1 = *(const ulonglong2*)&Bs[buf][kk][n0 + 64];
            u64 av[8] = { pack2(a0.x, a0.x), pack2(a0.y, a0.y),
                          pack2(a0.z, a0.z), pack2(a0.w, a0.w),
                          pack2(a1.x, a1.x), pack2(a1.y, a1.y),
                          pack2(a1.z, a1.z), pack2(a1.w, a1.w) };
            u64 bv[4] = { b0.x, b0.y, b1.x, b1.y };
            #pragma unroll
            for (int i = 0; i < 8; i++)
                #pragma unroll
                for (int j = 0; j < 4; j++)
                    ffma2(acc2[i][j], av[i], bv[j]);
        }
        if (s < S) {
            buf ^= 1;
            As[buf][lk+0][lr] = ra0.x; As[buf][lk+1][lr] = ra0.y; As[buf][lk+2][lr] = ra0.z; As[buf][lk+3][lr] = ra0.w;
            As[buf][lk+0][lr+64] = ra1.x; As[buf][lk+1][lr+64] = ra1.y; As[buf][lk+2][lr+64] = ra1.z; As[buf][lk+3][lr+64] = ra1.w;
            Bs[buf][lk+0][lr] = rb0.x; Bs[buf][lk+1][lr] = rb0.y; Bs[buf][lk+2][lr] = rb0.z; Bs[buf][lk+3][lr] = rb0.w;
            Bs[buf][lk+0][lr+64] = rb1.x; Bs[buf][lk+1][lr+64] = rb1.y; Bs[buf][lk+2][lr+64] = rb1.z; Bs[buf][lk+3][lr+64] = rb1.w;
            __syncthreads();
        }
    }

    #pragma unroll
    for (int i = 0; i < 8; i++) {
        int m = bm + m0 + ((i < 4) ? i : 60 + i);
        #pragma unroll
        for (int j = 0; j < 4; j++) {
            int n = bn + n0 + ((j < 2) ? 2*j : 60 + 2*j);
            float lo, hi; unpack2(acc2[i][j], lo, hi);
            g_gates[m * GATES + n]     = lo + bih[n]     + bhh[n];
            g_gates[m * GATES + n + 1] = hi + bih[n + 1] + bhh[n + 1];
        }
    }
}

// ================================================================================
// Kernel 3: logits GEMM + fused argmax (byte-identical to R12). grid(94,8).
// ================================================================================
__global__ __launch_bounds__(256) void k_logits_f(const float* __restrict__ Wout,
                                                  const float* __restrict__ bout) {
    __shared__ __align__(16) float As[2][16][132];
    __shared__ __align__(16) float Bs[2][16][132];
    __shared__ u64 sBest[128];
    const int tid = threadIdx.x;
    const int bm = blockIdx.y * 128, bn = blockIdx.x * 128;
    const int lr = tid >> 2;
    const int lk = (tid & 3) << 2;
    const int m0 = (tid >> 4) << 2;
    const int n0 = (tid & 15) << 2;
    u64 acc2[8][4] = {};
    float4 ra0, ra1, rb0, rb1;
    const float4 z4 = make_float4(0.f, 0.f, 0.f, 0.f);
    const int br0 = bn + lr, br1 = bn + lr + 64;
    const bool v0 = br0 < VOCABO, v1 = br1 < VOCABO;

    if (tid < 128) sBest[tid] = 0ULL;

    ra0 = *(const float4*)&g_h[(size_t)(bm + lr)      * 512 + lk];
    ra1 = *(const float4*)&g_h[(size_t)(bm + lr + 64) * 512 + lk];
    rb0 = v0 ? *(const float4*)&Wout[(size_t)br0 * 512 + lk] : z4;
    rb1 = v1 ? *(const float4*)&Wout[(size_t)br1 * 512 + lk] : z4;
    int buf = 0;
    As[0][lk+0][lr] = ra0.x; As[0][lk+1][lr] = ra0.y; As[0][lk+2][lr] = ra0.z; As[0][lk+3][lr] = ra0.w;
    As[0][lk+0][lr+64] = ra1.x; As[0][lk+1][lr+64] = ra1.y; As[0][lk+2][lr+64] = ra1.z; As[0][lk+3][lr+64] = ra1.w;
    Bs[0][lk+0][lr] = rb0.x; Bs[0][lk+1][lr] = rb0.y; Bs[0][lk+2][lr] = rb0.z; Bs[0][lk+3][lr] = rb0.w;
    Bs[0][lk+0][lr+64] = rb1.x; Bs[0][lk+1][lr+64] = rb1.y; Bs[0][lk+2][lr+64] = rb1.z; Bs[0][lk+3][lr+64] = rb1.w;
    __syncthreads();

    const int S = 32;                     // K = 512, BK = 16
    for (int s = 1; s <= S; s++) {
        if (s < S) {
            const int ka = s * 16 + lk;
            ra0 = *(const float4*)&g_h[(size_t)(bm + lr)      * 512 + ka];
            ra1 = *(const float4*)&g_h[(size_t)(bm + lr + 64) * 512 + ka];
            rb0 = v0 ? *(const float4*)&Wout[(size_t)br0 * 512 + ka] : z4;
            rb1 = v1 ? *(const float4*)&Wout[(size_t)br1 * 512 + ka] : z4;
        }
        #pragma unroll
        for (int kk = 0; kk < 16; kk++) {
            float4 a0 = *(const float4*)&As[buf][kk][m0];
            float4 a1 = *(const float4*)&As[buf][kk][m0 + 64];
            ulonglong2 b0 = *(const ulonglong2*)&Bs[buf][kk][n0];
            ulonglong2 b1 = *(const ulonglong2*)&Bs[buf][kk][n0 + 64];
            u64 av[8] = { pack2(a0.x, a0.x), pack2(a0.y, a0.y),
                          pack2(a0.z, a0.z), pack2(a0.w, a0.w),
                          pack2(a1.x, a1.x), pack2(a1.y, a1.y),
                          pack2(a1.z, a1.z), pack2(a1.w, a1.w) };
            u64 bv[4] = { b0.x, b0.y, b1.x, b1.y };
            #pragma unroll
            for (int i = 0; i < 8; i++)
                #pragma unroll
                for (int j = 0; j < 4; j++)
                    ffma2(acc2[i][j], av[i], bv[j]);
        }
        if (s < S) {
            buf ^= 1;
            As[buf][lk+0][lr] = ra0.x; As[buf][lk+1][lr] = ra0.y; As[buf][lk+2][lr] = ra0.z; As[buf][lk+3][lr] = ra0.w;
            As[buf][lk+0][lr+64] = ra1.x; As[buf][lk+1][lr+64] = ra1.y; As[buf][lk+2][lr+64] = ra1.z; As[buf][lk+3][lr+64] = ra1.w;
            Bs[buf][lk+0][lr] = rb0.x; Bs[buf][lk+1][lr] = rb0.y; Bs[buf][lk+2][lr] = rb0.z; Bs[buf][lk+3][lr] = rb0.w;
            Bs[buf][lk+0][lr+64] = rb1.x; Bs[buf][lk+1][lr+64] = rb1.y; Bs[buf][lk+2][lr+64] = rb1.z; Bs[buf][lk+3][lr+64] = rb1.w;
            __syncthreads();
        }
    }
    __syncthreads();

    // ---- fused argmax epilogue --------------------------------------------------
    #pragma unroll
    for (int i = 0; i < 8; i++) {
        const int mloc = m0 + ((i < 4) ? i : 60 + i);
        u64 best = 0ULL;
        #pragma unroll
        for (int j = 0; j < 4; j++) {
            int n = bn + n0 + ((j < 2) ? 2*j : 60 + 2*j);
            float lo, hi; unpack2(acc2[i][j], lo, hi);
            if (n < VOCABO) {
                u64 key = amax_key(lo + bout[n], n);
                if (key > best) best = key;
            }
            if (n + 1 < VOCABO) {
                u64 key = amax_key(hi + bout[n + 1], n + 1);
                if (key > best) best = key;
            }
        }
        atomicMax(&sBest[mloc], best);
    }
    __syncthreads();
    if (tid < 128) atomicMax(&g_amax[bm + tid], sBest[tid]);
}

// ================================================================================
// Kernel 4: LSTM pointwise; emits token emit_t (from live amax) then resets amax.
// ================================================================================
__global__ void k_point(float* __restrict__ out, int emit_t) {
    int idx = blockIdx.x * blockDim.x + threadIdx.x;
    int b = idx >> 9, n = idx & 511;
    const float* g = g_gates + b * GATES;
    float ig = sigm_f(g[n]);
    float fg = sigm_f(g[512 + n]);
    float gg = tanh_f(g[1024 + n]);
    float og = sigm_f(g[1536 + n]);
    float c = fg * g_c[idx] + ig * gg;
    g_c[idx] = c;
    g_h[idx] = og * tanh_f(c);
    if (idx < BATCH) {
        if (emit_t >= 0)
            out[idx * TSTEPS + emit_t] = (float)amax_idx(g_amax[idx]);
        g_amax[idx] = 0ULL;
    }
}

// -------- Kernel 5: final decode for the last step ------------------------------
__global__ void k_finish(float* __restrict__ out, int t) {
    int b = blockIdx.x * blockDim.x + threadIdx.x;
    if (b < BATCH)
        out[b * TSTEPS + t] = (float)amax_idx(g_amax[b]);
}

// ================================================================================
extern "C" void kernel_launch(void* const* d_in, const int* in_sizes, int n_in,
                              void* d_out, int out_size) {
    const float *img = 0, *W_feats = 0, *b_feats = 0, *W_ih = 0, *W_hh = 0,
                *b_ih = 0, *b_hh = 0, *emb = 0, *W_out = 0, *b_out = 0;
    for (int i = 0; i < n_in; i++) {
        const float* p = (const float*)d_in[i];
        switch (in_sizes[i]) {
            case 4194304: img = p; break;
            case 2097152: W_feats = p; break;
            case 512:     b_feats = p; break;
            case 1048576: if (!W_ih) W_ih = p; else W_hh = p; break;
            case 2048:    if (!b_ih) b_ih = p; else b_hh = p; break;
            case 6144000: emb = p; break;
            case 6142976: W_out = p; break;
            case 11998:   b_out = p; break;
            default: break;
        }
    }
    if (!img || !W_feats || !b_feats || !W_ih || !W_hh || !b_ih || !b_hh ||
        !emb || !W_out || !b_out) {
        img     = (const float*)d_in[0];
        W_feats = (const float*)d_in[1];
        b_feats = (const float*)d_in[2];
        W_ih    = (const float*)d_in[3];
        W_hh    = (const float*)d_in[4];
        b_ih    = (const float*)d_in[5];
        b_hh    = (const float*)d_in[6];
        emb     = (const float*)d_in[7];
        W_out   = (const float*)d_in[8];
        b_out   = (const float*)d_in[9];
    }
    float* out = (float*)d_out;

    // priming: img_vec (g_x) -> first LSTM cell
    k_prime <<<dim3(8, 16), 256>>>(img, W_feats, b_feats);
    k_gates <<<dim3(16, 8), 256>>>(W_ih, W_hh, b_ih, b_hh, emb, 0, /*use_emb=*/0);
    k_point <<<2048, 256>>>(out, -1);

    // 15 greedy decode steps: gates(emb gather+decode) -> point(emit t-1) -> logits
    for (int t = 0; t < TSTEPS; t++) {
        k_gates    <<<dim3(16, 8), 256>>>(W_ih, W_hh, b_ih, b_hh, emb, t, 1);
        k_point    <<<2048, 256>>>(out, t - 1);
        k_logits_f <<<dim3(94, 8), 256>>>(W_out, b_out);
    }
    k_finish <<<4, 256>>>(out, TSTEPS - 1);
}

// round 16
// speedup vs baseline: 1.7663x; 1.0343x over previous
#include <cuda_runtime.h>
#include <math.h>
#include <cstdint>

#define BATCH   1024
#define EMBD    512
#define RNND    512
#define GATES   2048
#define VOCABO  11998
#define FEATSD  4096
#define TSTEPS  15

typedef unsigned long long u64;

// ---------------- scratch (__device__ globals; no runtime allocation) ----------
__device__ float g_x[BATCH * EMBD];          // priming input only
__device__ float g_h[BATCH * RNND];
__device__ float g_c[BATCH * RNND];
__device__ float g_gA[BATCH * GATES];        // x @ W_ih^T partial
__device__ float g_gB[BATCH * GATES];        // h @ W_hh^T partial
__device__ u64   g_amax[BATCH];

// ---------------- packed f32x2 helpers ------------------------------------------
__device__ __forceinline__ u64 pack2(float lo, float hi) {
    u64 r; asm("mov.b64 %0, {%1, %2};" : "=l"(r) : "f"(lo), "f"(hi)); return r;
}
__device__ __forceinline__ void unpack2(u64 v, float& lo, float& hi) {
    asm("mov.b64 {%0, %1}, %2;" : "=f"(lo), "=f"(hi) : "l"(v));
}
__device__ __forceinline__ void ffma2(u64& d, u64 a, u64 b) {
    asm("fma.rn.f32x2 %0, %1, %2, %0;" : "+l"(d) : "l"(a), "l"(b));
}

// ---------------- activations / argmax keys -------------------------------------
__device__ __forceinline__ float sigm_f(float x) { return 1.0f / (1.0f + expf(-x)); }
__device__ __forceinline__ float tanh_f(float x) {
    float e = expf(-2.0f * fabsf(x));
    float t = (1.0f - e) / (1.0f + e);
    return copysignf(t, x);
}
__device__ __forceinline__ u64 amax_key(float v, int n) {
    unsigned u = __float_as_uint(v);
    u = (u & 0x80000000u) ? ~u : (u | 0x80000000u);
    return ((u64)u << 32) | (u64)(0xFFFFFFFFu - (unsigned)n);
}
__device__ __forceinline__ int amax_idx(u64 key) {
    return (int)(0xFFFFFFFFu - (unsigned)(key & 0xFFFFFFFFull));
}

// ================================================================================
// Kernel 1: g_x = relu(img[1024,4096] @ W_feats^T + b); zero h, c. (proven R12)
// ================================================================================
__global__ __launch_bounds__(256) void k_prime(const float* __restrict__ A,
                                               const float* __restrict__ Bw,
                                               const float* __restrict__ bias) {
    __shared__ __align__(16) float As[32][68];
    __shared__ __align__(16) float Bs[32][68];
    const int tid = threadIdx.x;
    const int bm = blockIdx.y * 64, bn = blockIdx.x * 64;
    const int lr = tid >> 3, lk = (tid & 7) << 2;
    const int m0 = (tid >> 4) << 2, n0 = (tid & 15) << 2;
    u64 acc2[4][2] = {};

    for (int s = 0; s < FEATSD / 32; s++) {
        const int ka = s * 32 + lk;
        float4 a0 = *(const float4*)&A [(size_t)(bm + lr)      * FEATSD + ka];
        float4 a1 = *(const float4*)&A [(size_t)(bm + lr + 32) * FEATSD + ka];
        float4 b0 = *(const float4*)&Bw[(size_t)(bn + lr)      * FEATSD + ka];
        float4 b1 = *(const float4*)&Bw[(size_t)(bn + lr + 32) * FEATSD + ka];
        __syncthreads();
        As[lk+0][lr] = a0.x; As[lk+1][lr] = a0.y; As[lk+2][lr] = a0.z; As[lk+3][lr] = a0.w;
        As[lk+0][lr+32] = a1.x; As[lk+1][lr+32] = a1.y; As[lk+2][lr+32] = a1.z; As[lk+3][lr+32] = a1.w;
        Bs[lk+0][lr] = b0.x; Bs[lk+1][lr] = b0.y; Bs[lk+2][lr] = b0.z; Bs[lk+3][lr] = b0.w;
        Bs[lk+0][lr+32] = b1.x; Bs[lk+1][lr+32] = b1.y; Bs[lk+2][lr+32] = b1.z; Bs[lk+3][lr+32] = b1.w;
        __syncthreads();
        #pragma unroll
        for (int kk = 0; kk < 32; kk++) {
            float4 a = *(const float4*)&As[kk][m0];
            ulonglong2 b = *(const ulonglong2*)&Bs[kk][n0];
            u64 av[4] = { pack2(a.x, a.x), pack2(a.y, a.y),
                          pack2(a.z, a.z), pack2(a.w, a.w) };
            #pragma unroll
            for (int i = 0; i < 4; i++) {
                ffma2(acc2[i][0], av[i], b.x);
                ffma2(acc2[i][1], av[i], b.y);
            }
        }
    }

    #pragma unroll
    for (int i = 0; i < 4; i++) {
        int m = bm + m0 + i;
        #pragma unroll
        for (int j = 0; j < 2; j++) {
            int n = bn + n0 + 2 * j;
            float lo, hi; unpack2(acc2[i][j], lo, hi);
            int idx = m * EMBD + n;
            g_x[idx]     = fmaxf(lo + bias[n],     0.0f);
            g_x[idx + 1] = fmaxf(hi + bias[n + 1], 0.0f);
            g_h[idx] = 0.0f; g_h[idx + 1] = 0.0f;
            g_c[idx] = 0.0f; g_c[idx + 1] = 0.0f;
        }
    }
}

// ================================================================================
// Kernel 2: gates GEMM half. grid(16,8,2) = 256 blocks, each K=512.
//   z=0: A = emb[word] gather (or g_x when priming), B = W_ih -> g_gA
//   z=1: A = g_h, B = W_hh -> g_gB
// Inner loop byte-identical to the proven R12 scheme (8x8/thread, BK=16 dbuf).
// ================================================================================
__global__ __launch_bounds__(256) void k_gates_half(const float* __restrict__ Wih,
                                                    const float* __restrict__ Whh,
                                                    const float* __restrict__ emb,
                                                    int t, int use_emb) {
    __shared__ __align__(16) float As[2][16][132];
    __shared__ __align__(16) float Bs[2][16][132];
    const int tid = threadIdx.x;
    const int bm = blockIdx.y * 128, bn = blockIdx.x * 128;
    const int z  = blockIdx.z;
    const int lr = tid >> 2;
    const int lk = (tid & 3) << 2;
    const int m0 = (tid >> 4) << 2;
    const int n0 = (tid & 15) << 2;
    u64 acc2[8][4] = {};
    float4 ra0, ra1, rb0, rb1;

    // resolve A-row base pointers and B matrix for this half
    const float* arow0;
    const float* arow1;
    const float* Bmat;
    if (z == 0) {
        if (use_emb) {
            int w0 = 1, w1 = 1;
            if (t > 0) {
                w0 = amax_idx(g_amax[bm + lr])      + 2;
                w1 = amax_idx(g_amax[bm + lr + 64]) + 2;
            }
            arow0 = emb + (size_t)w0 * EMBD;
            arow1 = emb + (size_t)w1 * EMBD;
        } else {
            arow0 = g_x + (size_t)(bm + lr)      * EMBD;
            arow1 = g_x + (size_t)(bm + lr + 64) * EMBD;
        }
        Bmat = Wih;
    } else {
        arow0 = g_h + (size_t)(bm + lr)      * RNND;
        arow1 = g_h + (size_t)(bm + lr + 64) * RNND;
        Bmat = Whh;
    }
    float* outp = (z == 0) ? g_gA : g_gB;

    ra0 = *(const float4*)&arow0[lk];
    ra1 = *(const float4*)&arow1[lk];
    rb0 = *(const float4*)&Bmat[(size_t)(bn + lr)      * 512 + lk];
    rb1 = *(const float4*)&Bmat[(size_t)(bn + lr + 64) * 512 + lk];
    int buf = 0;
    As[0][lk+0][lr] = ra0.x; As[0][lk+1][lr] = ra0.y; As[0][lk+2][lr] = ra0.z; As[0][lk+3][lr] = ra0.w;
    As[0][lk+0][lr+64] = ra1.x; As[0][lk+1][lr+64] = ra1.y; As[0][lk+2][lr+64] = ra1.z; As[0][lk+3][lr+64] = ra1.w;
    Bs[0][lk+0][lr] = rb0.x; Bs[0][lk+1][lr] = rb0.y; Bs[0][lk+2][lr] = rb0.z; Bs[0][lk+3][lr] = rb0.w;
    Bs[0][lk+0][lr+64] = rb1.x; Bs[0][lk+1][lr+64] = rb1.y; Bs[0][lk+2][lr+64] = rb1.z; Bs[0][lk+3][lr+64] = rb1.w;
    __syncthreads();

    const int S = 32;                     // K = 512, BK = 16
    for (int s = 1; s <= S; s++) {
        if (s < S) {
            const int ka = s * 16 + lk;
            ra0 = *(const float4*)&arow0[ka];
            ra1 = *(const float4*)&arow1[ka];
            rb0 = *(const float4*)&Bmat[(size_t)(bn + lr)      * 512 + ka];
            rb1 = *(const float4*)&Bmat[(size_t)(bn + lr + 64) * 512 + ka];
        }
        #pragma unroll
        for (int kk = 0; kk < 16; kk++) {
            float4 a0 = *(const float4*)&As[buf][kk][m0];
            float4 a1 = *(const float4*)&As[buf][kk][m0 + 64];
            ulonglong2 b0 = *(const ulonglong2*)&Bs[buf][kk][n0];
            ulonglong2 b1 = *(const ulonglong2*)&Bs[buf][kk][n0 + 64];
            u64 av[8] = { pack2(a0.x, a0.x), pack2(a0.y, a0.y),
                          pack2(a0.z, a0.z), pack2(a0.w, a0.w),
                          pack2(a1.x, a1.x), pack2(a1.y, a1.y),
                          pack2(a1.z, a1.z), pack2(a1.w, a1.w) };
            u64 bv[4] = { b0.x, b0.y, b1.x, b1.y };
            #pragma unroll
            for (int i = 0; i < 8; i++)
                #pragma unroll
                for (int j = 0; j < 4; j++)
                    ffma2(acc2[i][j], av[i], bv[j]);
        }
        if (s < S) {
            buf ^= 1;
            As[buf][lk+0][lr] = ra0.x; As[buf][lk+1][lr] = ra0.y; As[buf][lk+2][lr] = ra0.z; As[buf][lk+3][lr] = ra0.w;
            As[buf][lk+0][lr+64] = ra1.x; As[buf][lk+1][lr+64] = ra1.y; As[buf][lk+2][lr+64] = ra1.z; As[buf][lk+3][lr+64] = ra1.w;
            Bs[buf][lk+0][lr] = rb0.x; Bs[buf][lk+1][lr] = rb0.y; Bs[buf][lk+2][lr] = rb0.z; Bs[buf][lk+3][lr] = rb0.w;
            Bs[buf][lk+0][lr+64] = rb1.x; Bs[buf][lk+1][lr+64] = rb1.y; Bs[buf][lk+2][lr+64] = rb1.z; Bs[buf][lk+3][lr+64] = rb1.w;
            __syncthreads();
        }
    }

    #pragma unroll
    for (int i = 0; i < 8; i++) {
        int m = bm + m0 + ((i < 4) ? i : 60 + i);
        #pragma unroll
        for (int j = 0; j < 4; j++) {
            int n = bn + n0 + ((j < 2) ? 2*j : 60 + 2*j);
            float lo, hi; unpack2(acc2[i][j], lo, hi);
            outp[m * GATES + n]     = lo;
            outp[m * GATES + n + 1] = hi;
        }
    }
}

// ================================================================================
// Kernel 3: logits GEMM + fused argmax (byte-identical to R12). grid(94,8).
// ================================================================================
__global__ __launch_bounds__(256) void k_logits_f(const float* __restrict__ Wout,
                                                  const float* __restrict__ bout) {
    __shared__ __align__(16) float As[2][16][132];
    __shared__ __align__(16) float Bs[2][16][132];
    __shared__ u64 sBest[128];
    const int tid = threadIdx.x;
    const int bm = blockIdx.y * 128, bn = blockIdx.x * 128;
    const int lr = tid >> 2;
    const int lk = (tid & 3) << 2;
    const int m0 = (tid >> 4) << 2;
    const int n0 = (tid & 15) << 2;
    u64 acc2[8][4] = {};
    float4 ra0, ra1, rb0, rb1;
    const float4 z4 = make_float4(0.f, 0.f, 0.f, 0.f);
    const int br0 = bn + lr, br1 = bn + lr + 64;
    const bool v0 = br0 < VOCABO, v1 = br1 < VOCABO;

    if (tid < 128) sBest[tid] = 0ULL;

    ra0 = *(const float4*)&g_h[(size_t)(bm + lr)      * 512 + lk];
    ra1 = *(const float4*)&g_h[(size_t)(bm + lr + 64) * 512 + lk];
    rb0 = v0 ? *(const float4*)&Wout[(size_t)br0 * 512 + lk] : z4;
    rb1 = v1 ? *(const float4*)&Wout[(size_t)br1 * 512 + lk] : z4;
    int buf = 0;
    As[0][lk+0][lr] = ra0.x; As[0][lk+1][lr] = ra0.y; As[0][lk+2][lr] = ra0.z; As[0][lk+3][lr] = ra0.w;
    As[0][lk+0][lr+64] = ra1.x; As[0][lk+1][lr+64] = ra1.y; As[0][lk+2][lr+64] = ra1.z; As[0][lk+3][lr+64] = ra1.w;
    Bs[0][lk+0][lr] = rb0.x; Bs[0][lk+1][lr] = rb0.y; Bs[0][lk+2][lr] = rb0.z; Bs[0][lk+3][lr] = rb0.w;
    Bs[0][lk+0][lr+64] = rb1.x; Bs[0][lk+1][lr+64] = rb1.y; Bs[0][lk+2][lr+64] = rb1.z; Bs[0][lk+3][lr+64] = rb1.w;
    __syncthreads();

    const int S = 32;                     // K = 512, BK = 16
    for (int s = 1; s <= S; s++) {
        if (s < S) {
            const int ka = s * 16 + lk;
            ra0 = *(const float4*)&g_h[(size_t)(bm + lr)      * 512 + ka];
            ra1 = *(const float4*)&g_h[(size_t)(bm + lr + 64) * 512 + ka];
            rb0 = v0 ? *(const float4*)&Wout[(size_t)br0 * 512 + ka] : z4;
            rb1 = v1 ? *(const float4*)&Wout[(size_t)br1 * 512 + ka] : z4;
        }
        #pragma unroll
        for (int kk = 0; kk < 16; kk++) {
            float4 a0 = *(const float4*)&As[buf][kk][m0];
            float4 a1 = *(const float4*)&As[buf][kk][m0 + 64];
            ulonglong2 b0 = *(const ulonglong2*)&Bs[buf][kk][n0];
            ulonglong2 b1 = *(const ulonglong2*)&Bs[buf][kk][n0 + 64];
            u64 av[8] = { pack2(a0.x, a0.x), pack2(a0.y, a0.y),
                          pack2(a0.z, a0.z), pack2(a0.w, a0.w),
                          pack2(a1.x, a1.x), pack2(a1.y, a1.y),
                          pack2(a1.z, a1.z), pack2(a1.w, a1.w) };
            u64 bv[4] = { b0.x, b0.y, b1.x, b1.y };
            #pragma unroll
            for (int i = 0; i < 8; i++)
                #pragma unroll
                for (int j = 0; j < 4; j++)
                    ffma2(acc2[i][j], av[i], bv[j]);
        }
        if (s < S) {
            buf ^= 1;
            As[buf][lk+0][lr] = ra0.x; As[buf][lk+1][lr] = ra0.y; As[buf][lk+2][lr] = ra0.z; As[buf][lk+3][lr] = ra0.w;
            As[buf][lk+0][lr+64] = ra1.x; As[buf][lk+1][lr+64] = ra1.y; As[buf][lk+2][lr+64] = ra1.z; As[buf][lk+3][lr+64] = ra1.w;
            Bs[buf][lk+0][lr] = rb0.x; Bs[buf][lk+1][lr] = rb0.y; Bs[buf][lk+2][lr] = rb0.z; Bs[buf][lk+3][lr] = rb0.w;
            Bs[buf][lk+0][lr+64] = rb1.x; Bs[buf][lk+1][lr+64] = rb1.y; Bs[buf][lk+2][lr+64] = rb1.z; Bs[buf][lk+3][lr+64] = rb1.w;
            __syncthreads();
        }
    }
    __syncthreads();

    // ---- fused argmax epilogue --------------------------------------------------
    #pragma unroll
    for (int i = 0; i < 8; i++) {
        const int mloc = m0 + ((i < 4) ? i : 60 + i);
        u64 best = 0ULL;
        #pragma unroll
        for (int j = 0; j < 4; j++) {
            int n = bn + n0 + ((j < 2) ? 2*j : 60 + 2*j);
            float lo, hi; unpack2(acc2[i][j], lo, hi);
            if (n < VOCABO) {
                u64 key = amax_key(lo + bout[n], n);
                if (key > best) best = key;
            }
            if (n + 1 < VOCABO) {
                u64 key = amax_key(hi + bout[n + 1], n + 1);
                if (key > best) best = key;
            }
        }
        atomicMax(&sBest[mloc], best);
    }
    __syncthreads();
    if (tid < 128) atomicMax(&g_amax[bm + tid], sBest[tid]);
}

// ================================================================================
// Kernel 4: LSTM pointwise (sums both gate halves + biases);
// emits token emit_t from live amax, then resets amax.
// ================================================================================
__global__ void k_point(const float* __restrict__ bih,
                        const float* __restrict__ bhh,
                        float* __restrict__ out, int emit_t) {
    int idx = blockIdx.x * blockDim.x + threadIdx.x;
    int b = idx >> 9, n = idx & 511;
    const float* gA = g_gA + b * GATES;
    const float* gB = g_gB + b * GATES;
    float vi = gA[n]        + gB[n]        + bih[n]        + bhh[n];
    float vf = gA[512 + n]  + gB[512 + n]  + bih[512 + n]  + bhh[512 + n];
    float vg = gA[1024 + n] + gB[1024 + n] + bih[1024 + n] + bhh[1024 + n];
    float vo = gA[1536 + n] + gB[1536 + n] + bih[1536 + n] + bhh[1536 + n];
    float ig = sigm_f(vi);
    float fg = sigm_f(vf);
    float gg = tanh_f(vg);
    float og = sigm_f(vo);
    float c = fg * g_c[idx] + ig * gg;
    g_c[idx] = c;
    g_h[idx] = og * tanh_f(c);
    if (idx < BATCH) {
        if (emit_t >= 0)
            out[idx * TSTEPS + emit_t] = (float)amax_idx(g_amax[idx]);
        g_amax[idx] = 0ULL;
    }
}

// -------- Kernel 5: final decode for the last step ------------------------------
__global__ void k_finish(float* __restrict__ out, int t) {
    int b = blockIdx.x * blockDim.x + threadIdx.x;
    if (b < BATCH)
        out[b * TSTEPS + t] = (float)amax_idx(g_amax[b]);
}

// ================================================================================
extern "C" void kernel_launch(void* const* d_in, const int* in_sizes, int n_in,
                              void* d_out, int out_size) {
    const float *img = 0, *W_feats = 0, *b_feats = 0, *W_ih = 0, *W_hh = 0,
                *b_ih = 0, *b_hh = 0, *emb = 0, *W_out = 0, *b_out = 0;
    for (int i = 0; i < n_in; i++) {
        const float* p = (const float*)d_in[i];
        switch (in_sizes[i]) {
            case 4194304: img = p; break;
            case 2097152: W_feats = p; break;
            case 512:     b_feats = p; break;
            case 1048576: if (!W_ih) W_ih = p; else W_hh = p; break;
            case 2048:    if (!b_ih) b_ih = p; else b_hh = p; break;
            case 6144000: emb = p; break;
            case 6142976: W_out = p; break;
            case 11998:   b_out = p; break;
            default: break;
        }
    }
    if (!img || !W_feats || !b_feats || !W_ih || !W_hh || !b_ih || !b_hh ||
        !emb || !W_out || !b_out) {
        img     = (const float*)d_in[0];
        W_feats = (const float*)d_in[1];
        b_feats = (const float*)d_in[2];
        W_ih    = (const float*)d_in[3];
        W_hh    = (const float*)d_in[4];
        b_ih    = (const float*)d_in[5];
        b_hh    = (const float*)d_in[6];
        emb     = (const float*)d_in[7];
        W_out   = (const float*)d_in[8];
        b_out   = (const float*)d_in[9];
    }
    float* out = (float*)d_out;

    // priming: img_vec (g_x) -> first LSTM cell
    k_prime      <<<dim3(8, 16), 256>>>(img, W_feats, b_feats);
    k_gates_half <<<dim3(16, 8, 2), 256>>>(W_ih, W_hh, emb, 0, /*use_emb=*/0);
    k_point      <<<2048, 256>>>(b_ih, b_hh, out, -1);

    // 15 greedy decode steps
    for (int t = 0; t < TSTEPS; t++) {
        k_gates_half <<<dim3(16, 8, 2), 256>>>(W_ih, W_hh, emb, t, 1);
        k_point      <<<2048, 256>>>(b_ih, b_hh, out, t - 1);
        k_logits_f   <<<dim3(94, 8), 256>>>(W_out, b_out);
    }
    k_finish <<<4, 256>>>(out, TSTEPS - 1);
}